// round 2
// baseline (speedup 1.0000x reference)
#include <cuda_runtime.h>
#include <cstdint>

#define BSZ    64
#define BEAM   8
#define VOCAB  50257
#define KTOP   16
#define ROWS   (BSZ * BEAM)
#define THREADS 256

// Scratch between stages (allocation-free: __device__ globals)
__device__ float g_s1val[ROWS][KTOP];
__device__ int   g_s1idx[ROWS][KTOP];

// float -> order-preserving uint32 (larger uint == larger float)
__device__ __forceinline__ unsigned ford(float f) {
    unsigned u = __float_as_uint(f);
    return (u & 0x80000000u) ? ~u : (u | 0x80000000u);
}
__device__ __forceinline__ float funord(unsigned u) {
    return __uint_as_float((u & 0x80000000u) ? (u ^ 0x80000000u) : ~u);
}
__device__ __forceinline__ unsigned long long umax64(unsigned long long a, unsigned long long b) {
    return a > b ? a : b;
}

// key = (ordered_value << 32) | ~index  -> max key == (max value, min index): matches jax.lax.top_k ties
__device__ __forceinline__ unsigned long long mkkey(float v, unsigned idx) {
    return ((unsigned long long)ford(v) << 32) | (unsigned)(~idx);
}

__device__ __forceinline__ void insert1(float v, unsigned idx,
                                        unsigned long long* key,
                                        unsigned long long& kmin, int& smin) {
    unsigned long long kk = mkkey(v, idx);
    if (kk > kmin) {
        key[smin] = kk;
        kmin = key[0]; smin = 0;
#pragma unroll
        for (int s = 1; s < KTOP; s++)
            if (key[s] < kmin) { kmin = key[s]; smin = s; }
    }
}

__device__ __forceinline__ void insert4(float4 v, float add, int gi,
                                        unsigned long long* key,
                                        unsigned long long& kmin, int& smin) {
    insert1(v.x + add, (unsigned)(gi + 0), key, kmin, smin);
    insert1(v.y + add, (unsigned)(gi + 1), key, kmin, smin);
    insert1(v.z + add, (unsigned)(gi + 2), key, kmin, smin);
    insert1(v.w + add, (unsigned)(gi + 3), key, kmin, smin);
}

__global__ __launch_bounds__(THREADS)
void stage1_topk(const float* __restrict__ lprobs,
                 const float* __restrict__ scores,
                 const int* __restrict__ stepp, int sdim) {
    const int r   = blockIdx.x;      // (b, beam) row
    const int tid = threadIdx.x;

    int step = *stepp;
    if (step < 0 || step > sdim) step = sdim;   // defensive clamp

    float add = 0.0f;
    if (step > 0) add = scores[r * sdim + (step - 1)];

    const float* base = lprobs + (size_t)r * VOCAB;

    // Alignment peel: VOCAB is odd so row bases are only 4B-aligned.
    const uintptr_t addr = (uintptr_t)base;
    const int pre  = (int)(((16u - (unsigned)(addr & 15u)) & 15u) >> 2);  // 0..3
    const int NV4  = (VOCAB - pre) / 4;                                    // aligned float4 count
    const int tail = VOCAB - pre - NV4 * 4;                                // 0..3
    const float4* b4 = (const float4*)(base + pre);

    // per-thread register-resident top-16
    unsigned long long key[KTOP];
#pragma unroll
    for (int s = 0; s < KTOP; s++) key[s] = 0ull;
    unsigned long long kmin = 0ull;
    int smin = 0;

    // scalar prologue (0..3 elems) + scalar tail (0..3 elems), spread over first threads
    if (tid < pre)
        insert1(base[tid] + add, (unsigned)tid, key, kmin, smin);
    if (tid >= 4 && tid < 4 + tail) {
        const int gi = pre + NV4 * 4 + (tid - 4);
        insert1(base[gi] + add, (unsigned)gi, key, kmin, smin);
    }

    // main vectorized stream, unrolled x2 for MLP
    int i = tid;
    for (; i + THREADS < NV4; i += 2 * THREADS) {
        float4 a = b4[i];
        float4 c = b4[i + THREADS];
        insert4(a, add, pre + i * 4, key, kmin, smin);
        insert4(c, add, pre + (i + THREADS) * 4, key, kmin, smin);
    }
    for (; i < NV4; i += THREADS) {
        float4 a = b4[i];
        insert4(a, add, pre + i * 4, key, kmin, smin);
    }

    // 16 rounds of block argmax; keys are unique (index embedded), owner invalidates.
    __shared__ unsigned long long red[THREADS / 32];
    __shared__ unsigned long long winner_s;

    const int lane = tid & 31;
    const int wid  = tid >> 5;

    for (int rr = 0; rr < KTOP; rr++) {
        unsigned long long lm = key[0];
#pragma unroll
        for (int s = 1; s < KTOP; s++) lm = umax64(lm, key[s]);
#pragma unroll
        for (int off = 16; off; off >>= 1)
            lm = umax64(lm, __shfl_down_sync(0xffffffffu, lm, off));
        if (lane == 0) red[wid] = lm;
        __syncthreads();
        if (tid == 0) {
            unsigned long long w = red[0];
#pragma unroll
            for (int s = 1; s < THREADS / 32; s++) w = umax64(w, red[s]);
            winner_s = w;
            g_s1val[r][rr] = funord((unsigned)(w >> 32));
            g_s1idx[r][rr] = (int)(~(unsigned)(w & 0xffffffffu));
        }
        __syncthreads();
        unsigned long long w = winner_s;
#pragma unroll
        for (int s = 0; s < KTOP; s++)
            if (key[s] == w) key[s] = 0ull;
        __syncthreads();
    }
}

__global__ __launch_bounds__(BEAM * KTOP)
void stage2_final(float* __restrict__ out, const int* __restrict__ stepp, int sdim) {
    const int b = blockIdx.x;
    const int j = threadIdx.x;           // flat candidate 0..127

    int step = *stepp;
    if (step < 0 || step > sdim) step = sdim;

    float* out_scores = out;
    float* out_idx    = out + BSZ * KTOP;
    float* out_beam   = out + 2 * BSZ * KTOP;

    if (step == 0) {
        if (j < KTOP) {
            out_scores[b * KTOP + j] = g_s1val[b * BEAM + 0][j];
            out_idx[b * KTOP + j]    = (float)g_s1idx[b * BEAM + 0][j];
            out_beam[b * KTOP + j]   = 0.0f;
        }
        return;
    }

    const int beam = j >> 4;
    const int pos  = j & 15;
    const float v  = g_s1val[b * BEAM + beam][pos] - (float)(pos + 1) * 0.5f;
    unsigned long long kk = mkkey(v, (unsigned)j);

    __shared__ unsigned long long red[4];
    __shared__ unsigned long long winner_s;
    const int lane = j & 31;

    for (int rr = 0; rr < KTOP; rr++) {
        unsigned long long lm = kk;
#pragma unroll
        for (int off = 16; off; off >>= 1)
            lm = umax64(lm, __shfl_down_sync(0xffffffffu, lm, off));
        if (lane == 0) red[j >> 5] = lm;
        __syncthreads();
        if (j == 0) {
            unsigned long long w = red[0];
            w = umax64(w, red[1]); w = umax64(w, red[2]); w = umax64(w, red[3]);
            winner_s = w;
        }
        __syncthreads();
        if (kk == winner_s) {   // unique keys -> exactly one winner
            out_scores[b * KTOP + rr] = v;
            out_idx[b * KTOP + rr]    = (float)g_s1idx[b * BEAM + beam][pos];
            out_beam[b * KTOP + rr]   = (float)beam;
            kk = 0ull;
        }
        __syncthreads();
    }
}

extern "C" void kernel_launch(void* const* d_in, const int* in_sizes, int n_in,
                              void* d_out, int out_size) {
    const float* lprobs = (const float*)d_in[0];
    const float* scores = (const float*)d_in[1];
    const int*   stepp  = (const int*)d_in[2];
    const int sdim = in_sizes[1] / ROWS;   // scores last-dim length (=5)

    stage1_topk<<<ROWS, THREADS>>>(lprobs, scores, stepp, sdim);
    stage2_final<<<BSZ, BEAM * KTOP>>>((float*)d_out, stepp, sdim);
}

// round 3
// speedup vs baseline: 2.6459x; 2.6459x over previous
#include <cuda_runtime.h>
#include <cstdint>

#define BSZ    64
#define BEAM   8
#define VOCAB  50257
#define KTOP   16
#define ROWS   (BSZ * BEAM)
#define THREADS 256
#define CAP    2336          // 256 carry + 2048/iter + slack

// Inter-CTA scratch (allocation-free)
__device__ float g_s1val[ROWS][KTOP];
__device__ int   g_s1idx[ROWS][KTOP];
__device__ int   g_arrive[BSZ];   // zero-init; finisher resets -> graph-replay safe

__device__ __forceinline__ unsigned ford(float f) {
    unsigned u = __float_as_uint(f);
    return u ^ ((unsigned)((int)u >> 31) | 0x80000000u);
}
__device__ __forceinline__ float funord(unsigned u) {
    return __uint_as_float((u & 0x80000000u) ? (u ^ 0x80000000u) : ~u);
}
__device__ __forceinline__ unsigned long long umax64(unsigned long long a, unsigned long long b) {
    return a > b ? a : b;
}
__device__ __forceinline__ float vloadf(const float* p) { return *(const volatile float*)p; }
__device__ __forceinline__ int   vloadi(const int*   p) { return *(const volatile int*)p; }

// Exact top-16 of buf[0..C), winners (descending key order) into win[0..15].
// Winners are zeroed inside buf. Must be called by all 256 threads.
__device__ void compact16(unsigned long long* buf, int C,
                          unsigned long long* win, unsigned long long* red8,
                          unsigned long long* winner_s, int tid, int lane, int wid) {
    for (int r = 0; r < KTOP; r++) {
        unsigned long long lm = 0ull;
        for (int e = tid; e < C; e += THREADS) lm = umax64(lm, buf[e]);
#pragma unroll
        for (int off = 16; off; off >>= 1)
            lm = umax64(lm, __shfl_down_sync(0xffffffffu, lm, off));
        if (lane == 0) red8[wid] = lm;
        __syncthreads();
        if (tid == 0) {
            unsigned long long w = red8[0];
#pragma unroll
            for (int s = 1; s < THREADS / 32; s++) w = umax64(w, red8[s]);
            win[r] = w;
            *winner_s = w;
        }
        __syncthreads();
        unsigned long long w = *winner_s;
        for (int e = tid; e < C; e += THREADS)
            if (buf[e] == w) buf[e] = 0ull;   // keys unique -> exactly one match
        __syncthreads();
    }
}

// Warp-aggregated append of survivors into shared buffer.
__device__ __forceinline__ void appendB(bool p, unsigned ord, unsigned idx,
                                        unsigned long long* buf, int* cnt, int lane) {
    unsigned m = __ballot_sync(0xffffffffu, p);
    if (m) {
        int leader = __ffs(m) - 1;
        int basec = 0;
        if (lane == leader) basec = atomicAdd(cnt, __popc(m));
        basec = __shfl_sync(0xffffffffu, basec, leader);
        if (p) {
            unsigned long long kk = ((unsigned long long)ord << 32) | (unsigned)~idx;
            buf[basec + __popc(m & ((1u << lane) - 1u))] = kk;
        }
    }
}

__global__ __launch_bounds__(THREADS)
void dss_kernel(const float* __restrict__ lprobs,
                const float* __restrict__ scores,
                const int* __restrict__ stepp, int sdim,
                float* __restrict__ out) {
    __shared__ unsigned long long buf[CAP];
    __shared__ unsigned long long win[KTOP];
    __shared__ unsigned long long red8[THREADS / 32];
    __shared__ unsigned long long winner_s;
    __shared__ unsigned long long Tsh;
    __shared__ int cnt;
    __shared__ int lastflag;

    const int r    = blockIdx.x;      // (batch, beam) row
    const int b    = r / BEAM;
    const int tid  = threadIdx.x;
    const int lane = tid & 31;
    const int wid  = tid >> 5;

    int step = *stepp;
    if (step < 0 || step > sdim) step = sdim;    // defensive clamp
    const float add = (step > 0) ? scores[r * sdim + (step - 1)] : 0.0f;

    if (tid == 0) { cnt = 0; Tsh = 0ull; }
    __syncthreads();

    const float* base = lprobs + (size_t)r * VOCAB;
    const uintptr_t addr = (uintptr_t)base;
    const int pre  = (int)(((16u - (unsigned)(addr & 15u)) & 15u) >> 2);  // 0..3
    const int NV4  = (VOCAB - pre) >> 2;
    const int tail = VOCAB - pre - (NV4 << 2);
    const float4* b4 = (const float4*)(base + pre);

    // prologue (0..3) + tail (0..3) scalars; T==0 so all survive
    {
        bool p = (tid < pre);
        float v = p ? base[tid] : 0.0f;
        appendB(p, ford(v + add), (unsigned)tid, buf, &cnt, lane);
        int t2 = tid - 64;
        bool q = (t2 >= 0 && t2 < tail);
        int gi = pre + (NV4 << 2) + (q ? t2 : 0);
        float v2 = q ? base[gi] : 0.0f;
        appendB(q, ford(v2 + add), (unsigned)gi, buf, &cnt, lane);
    }
    __syncthreads();

    unsigned Thi = 0u;
    const int NITER = (NV4 + 2 * THREADS - 1) / (2 * THREADS);

    for (int it = 0; it < NITER; it++) {
        const int i0 = it * 2 * THREADS + tid;
        const int i1 = i0 + THREADS;
        const bool g0 = i0 < NV4;
        const bool g1 = i1 < NV4;
        float4 a = make_float4(0.f, 0.f, 0.f, 0.f);
        float4 c = make_float4(0.f, 0.f, 0.f, 0.f);
        if (g0) a = __ldcs(b4 + i0);
        if (g1) c = __ldcs(b4 + i1);

        {
            const unsigned gi = (unsigned)(pre + i0 * 4);
            unsigned o0 = ford(a.x + add), o1 = ford(a.y + add);
            unsigned o2 = ford(a.z + add), o3 = ford(a.w + add);
            appendB(g0 && o0 >= Thi, o0, gi + 0, buf, &cnt, lane);
            appendB(g0 && o1 >= Thi, o1, gi + 1, buf, &cnt, lane);
            appendB(g0 && o2 >= Thi, o2, gi + 2, buf, &cnt, lane);
            appendB(g0 && o3 >= Thi, o3, gi + 3, buf, &cnt, lane);
        }
        {
            const unsigned gi = (unsigned)(pre + i1 * 4);
            unsigned o0 = ford(c.x + add), o1 = ford(c.y + add);
            unsigned o2 = ford(c.z + add), o3 = ford(c.w + add);
            appendB(g1 && o0 >= Thi, o0, gi + 0, buf, &cnt, lane);
            appendB(g1 && o1 >= Thi, o1, gi + 1, buf, &cnt, lane);
            appendB(g1 && o2 >= Thi, o2, gi + 2, buf, &cnt, lane);
            appendB(g1 && o3 >= Thi, o3, gi + 3, buf, &cnt, lane);
        }

        __syncthreads();
        if (cnt > 256) {                       // uniform: read post-barrier
            compact16(buf, cnt, win, red8, &winner_s, tid, lane, wid);
            if (tid < KTOP) buf[tid] = win[tid];
            if (tid == 0) { cnt = KTOP; Tsh = win[KTOP - 1]; }
            __syncthreads();
        }
        Thi = (unsigned)(Tsh >> 32);
    }

    // final exact selection for this row
    __syncthreads();
    compact16(buf, cnt, win, red8, &winner_s, tid, lane, wid);
    if (tid < KTOP) {
        unsigned long long w = win[tid];
        g_s1val[r][tid] = funord((unsigned)(w >> 32));
        g_s1idx[r][tid] = (int)~((unsigned)w);
    }
    __threadfence();
    __syncthreads();

    // last CTA per batch runs the final 128 -> 16 selection
    if (tid == 0) lastflag = (atomicAdd(&g_arrive[b], 1) == BEAM - 1) ? 1 : 0;
    __syncthreads();
    if (!lastflag) return;
    __threadfence();   // acquire: see all beams' g_s1 writes

    float* out_scores = out;
    float* out_idx    = out + BSZ * KTOP;
    float* out_beam   = out + 2 * BSZ * KTOP;

    if (step == 0) {
        if (tid < KTOP) {
            out_scores[b * KTOP + tid] = vloadf(&g_s1val[b * BEAM][tid]);
            out_idx[b * KTOP + tid]    = (float)vloadi(&g_s1idx[b * BEAM][tid]);
            out_beam[b * KTOP + tid]   = 0.0f;
        }
        if (tid == 0) g_arrive[b] = 0;
        return;
    }

    if (tid < BEAM * KTOP) {
        const int beam = tid >> 4, pos = tid & 15;
        const float v = vloadf(&g_s1val[b * BEAM + beam][pos]) - (float)(pos + 1) * 0.5f;
        buf[tid] = ((unsigned long long)ford(v) << 32) | (unsigned)~((unsigned)tid);
    }
    __syncthreads();
    compact16(buf, BEAM * KTOP, win, red8, &winner_s, tid, lane, wid);
    if (tid < KTOP) {
        unsigned long long w = win[tid];
        const int j = (int)~((unsigned)w);       // flat candidate, matches reference fi
        const int beam = j >> 4, pos = j & 15;
        out_scores[b * KTOP + tid] = funord((unsigned)(w >> 32));
        out_idx[b * KTOP + tid]    = (float)vloadi(&g_s1idx[b * BEAM + beam][pos]);
        out_beam[b * KTOP + tid]   = (float)beam;
    }
    if (tid == 0) g_arrive[b] = 0;
}

extern "C" void kernel_launch(void* const* d_in, const int* in_sizes, int n_in,
                              void* d_out, int out_size) {
    const float* lprobs = (const float*)d_in[0];
    const float* scores = (const float*)d_in[1];
    const int*   stepp  = (const int*)d_in[2];
    const int sdim = in_sizes[1] / ROWS;

    dss_kernel<<<ROWS, THREADS>>>(lprobs, scores, stepp, sdim, (float*)d_out);
}